// round 14
// baseline (speedup 1.0000x reference)
#include <cuda_runtime.h>

// GaussianBlur2D: depthwise 11x11 Gaussian blur, reflect padding.
// x: (16, 64, 512, 512) fp32, sigma: (1,) fp32.
//
// Round-9 architecture (best: 377.9us) with RPT=2 for higher occupancy:
//   - 12-row sliding float4 register window (outputs y,y+1 need y-5..y+6)
//   - vblur rows -> smem via scalar STS (offset-5 layout); horizontal via
//     4 aligned LDS.128; mirrored halo written by edge threads only
//   - ~80 regs -> __launch_bounds__(128,6): 24 warps/SM (+26% vs round 9)
//   - sigma==1.5 fast path with compile-time constant weights; generic
//     runtime-sigma path otherwise
// g2d[i][j] = (h[i]/S)*(h[j]/S) with S = sum(h)  == reference's 2D kernel.

#define KS    11
#define IMG   512
#define NT    128      // threads per block; NT*4 == IMG
#define RPT   2        // output rows per iteration
#define WIN   12       // KS + RPT - 1
#define STRIP 128      // output rows per block
#define SVW   528      // smem row: [0..4] halo, [5..516] data, [517..521] halo

__device__ __forceinline__ int refl(int i) {
    i = (i < 0) ? -i : i;
    return (i >= IMG) ? (2 * IMG - 2 - i) : i;
}

template<bool SPEC>
__device__ __forceinline__ void blur_body(const float* __restrict__ img,
                                          float* __restrict__ oimg,
                                          int t, int y0, float sig,
                                          float (*s_v)[SVW]) {
    const int x = t << 2;                  // this thread owns columns x..x+3
    const bool edge = (t < 2) || (t >= 126);

    float w[KS];
    if constexpr (SPEC) {
        // sigma = 1.5 (+1e-6), normalized 1D Gaussian
        w[0]  = 0.00102838f; w[1] = 0.00759878f; w[2]  = 0.03600090f;
        w[3]  = 0.10935980f; w[4] = 0.21300625f; w[5]  = 0.26601207f;
        w[6]  = 0.21300625f; w[7] = 0.10935980f; w[8]  = 0.03600090f;
        w[9]  = 0.00759878f; w[10] = 0.00102838f;
    } else {
        float s = fabsf(sig) + 1e-6f;
        float inv = 1.0f / (2.0f * s * s);
        float sum = 0.0f;
        #pragma unroll
        for (int j = 0; j < KS; j++) {
            float r = (float)j - (float)(KS - 1) * 0.5f;
            w[j] = __expf(-r * r * inv);
            sum += w[j];
        }
        float rs = 1.0f / sum;
        #pragma unroll
        for (int j = 0; j < KS; j++) w[j] *= rs;
    }

    // win[k] = raw input row (y0 + k - 5), k = 0..11
    float4 win[WIN];
    #pragma unroll
    for (int k = 0; k < WIN; k++)
        win[k] = *(const float4*)(img + (size_t)refl(y0 + k - 5) * IMG + x);

    for (int yb = 0; yb < STRIP; yb += RPT) {
        const int y = y0 + yb;

        // Prefetch next RPT raw rows (rows y+7, y+8); overlaps math below.
        float4 pre[RPT];
        #pragma unroll
        for (int r = 0; r < RPT; r++)
            pre[r] = *(const float4*)(img + (size_t)refl(y + KS - 4 + r) * IMG + x);

        // ---- vertical 11-tap (registers only) ----
        #pragma unroll
        for (int r = 0; r < RPT; r++) {
            float a[4] = {0.f, 0.f, 0.f, 0.f};
            #pragma unroll
            for (int i = 0; i < KS; i++) {
                const float  wi = w[i];
                const float4 v  = win[r + i];
                a[0] = fmaf(wi, v.x, a[0]);
                a[1] = fmaf(wi, v.y, a[1]);
                a[2] = fmaf(wi, v.z, a[2]);
                a[3] = fmaf(wi, v.w, a[3]);
            }
            float* sv = s_v[r];
            #pragma unroll
            for (int c = 0; c < 4; c++)        // scalar STS (offset 5+x unaligned)
                sv[5 + x + c] = a[c];

            if (edge) {  // mirrored halo: col -c <- col c ; col 512+k <- col 510-k
                #pragma unroll
                for (int c = 0; c < 4; c++) {
                    const int xc = x + c;
                    if (xc >= 1   && xc <= 5)   sv[5 - xc]    = a[c];
                    if (xc >= 506 && xc <= 510) sv[1027 - xc] = a[c];
                }
            }
        }
        __syncthreads();

        // ---- horizontal 11-tap: 4 aligned LDS.128 -> 4 outputs per row ----
        #pragma unroll
        for (int r = 0; r < RPT; r++) {
            const float4* vp = (const float4*)&s_v[r][x];   // x mult of 4 -> aligned
            const float4 A = vp[0], B = vp[1], C = vp[2], D = vp[3];
            const float v[16] = {A.x, A.y, A.z, A.w,
                                 B.x, B.y, B.z, B.w,
                                 C.x, C.y, C.z, C.w,
                                 D.x, D.y, D.z, D.w};
            float o0 = 0.f, o1 = 0.f, o2 = 0.f, o3 = 0.f;
            #pragma unroll
            for (int j = 0; j < KS; j++) {
                const float wj = w[j];
                o0 = fmaf(wj, v[j],     o0);
                o1 = fmaf(wj, v[j + 1], o1);
                o2 = fmaf(wj, v[j + 2], o2);
                o3 = fmaf(wj, v[j + 3], o3);
            }
            *(float4*)(oimg + (size_t)(y + r) * IMG + x) = make_float4(o0, o1, o2, o3);
        }
        __syncthreads();

        // ---- slide the window down by RPT rows ----
        #pragma unroll
        for (int k = 0; k < WIN - RPT; k++) win[k] = win[k + RPT];
        #pragma unroll
        for (int r = 0; r < RPT; r++)       win[WIN - RPT + r] = pre[r];
    }
}

__global__ __launch_bounds__(NT, 6)
void gaussian_blur_kernel(const float* __restrict__ in, float* __restrict__ out,
                          const float* __restrict__ sigma) {
    __shared__ __align__(16) float s_v[RPT][SVW];

    const int t = threadIdx.x;
    const int plane = blockIdx.x >> 2;
    const int y0 = (blockIdx.x & 3) * STRIP;
    const float* __restrict__ img  = in  + (size_t)plane * (IMG * IMG);
    float*       __restrict__ oimg = out + (size_t)plane * (IMG * IMG);

    const float sig = sigma[0];
    if (fabsf(fabsf(sig) - 1.5f) < 1e-4f) {
        blur_body<true >(img, oimg, t, y0, sig, s_v);
    } else {
        blur_body<false>(img, oimg, t, y0, sig, s_v);
    }
}

extern "C" void kernel_launch(void* const* d_in, const int* in_sizes, int n_in,
                              void* d_out, int out_size) {
    const float* x     = (const float*)d_in[0];
    const float* sigma = (const float*)d_in[1];
    float*       out   = (float*)d_out;

    const int n_img = in_sizes[0] / (IMG * IMG);   // B*C planes

    const int strips = IMG / STRIP;                // 4
    gaussian_blur_kernel<<<n_img * strips, NT>>>(x, out, sigma);
}

// round 15
// speedup vs baseline: 1.5559x; 1.5559x over previous
#include <cuda_runtime.h>

// GaussianBlur2D: depthwise 11x11 Gaussian blur, reflect padding.
// x: (16, 64, 512, 512) fp32, sigma: (1,) fp32.
//
// Round-9 body (best: 377.9us) + forced FFMA-immediate encoding:
//   ptxas CSE previously materialized the 6 weight constants into registers
//   (FFMA reg-form, rt_SMSP=2). Here every (tap, lane, pass) site gets a
//   DISTINCT constant (perturbed <=15 ulp, rel <1e-6) -- 88 distinct fp32
//   constants cannot be register-materialized, forcing FFMA R,R,IMM,R
//   (rt_SMSP=1, 2x fma throughput).
//   - vertical 11-tap in registers (14-row sliding float4 window)
//   - vblur -> smem via scalar STS; horizontal via 4 aligned LDS.128
//   - sigma==1.5 fast path; generic runtime-sigma path otherwise
// g2d[i][j] = (h[i]/S)*(h[j]/S) with S = sum(h)  == reference's 2D kernel.

#define KS    11
#define IMG   512
#define NT    128
#define RPT   4
#define STRIP 128
#define SVW   528      // smem row: [0..4] halo, [5..516] data, [517..521] halo

// fma.rn.f32 acc = v * <imm> + acc   (imm as PTX hex float literal)
#define FMA_IMM(acc, v, HEX) \
    asm("fma.rn.f32 %0, %1, " HEX ", %0;" : "+f"(acc) : "f"(v))

// ---- per-site weight constants: base value + variant ulps (<=15) ----
// W0 = 0.00102838  (0x3A86CAB4)
#define W0V_0  "0f3A86CAB4"
#define W0V_1  "0f3A86CAB5"
#define W0V_2  "0f3A86CAB6"
#define W0V_3  "0f3A86CAB7"
#define W0V_4  "0f3A86CAB8"
#define W0V_5  "0f3A86CAB9"
#define W0V_6  "0f3A86CABA"
#define W0V_7  "0f3A86CABB"
#define W0V_8  "0f3A86CABC"
#define W0V_9  "0f3A86CABD"
#define W0V_10 "0f3A86CABE"
#define W0V_11 "0f3A86CABF"
#define W0V_12 "0f3A86CAC0"
#define W0V_13 "0f3A86CAC1"
#define W0V_14 "0f3A86CAC2"
#define W0V_15 "0f3A86CAC3"
// W1 = 0.00759878  (0x3BF8FF33)
#define W1V_0  "0f3BF8FF33"
#define W1V_1  "0f3BF8FF34"
#define W1V_2  "0f3BF8FF35"
#define W1V_3  "0f3BF8FF36"
#define W1V_4  "0f3BF8FF37"
#define W1V_5  "0f3BF8FF38"
#define W1V_6  "0f3BF8FF39"
#define W1V_7  "0f3BF8FF3A"
#define W1V_8  "0f3BF8FF3B"
#define W1V_9  "0f3BF8FF3C"
#define W1V_10 "0f3BF8FF3D"
#define W1V_11 "0f3BF8FF3E"
#define W1V_12 "0f3BF8FF3F"
#define W1V_13 "0f3BF8FF40"
#define W1V_14 "0f3BF8FF41"
#define W1V_15 "0f3BF8FF42"
// W2 = 0.03600069  (0x3D137578)
#define W2V_0  "0f3D137578"
#define W2V_1  "0f3D137579"
#define W2V_2  "0f3D13757A"
#define W2V_3  "0f3D13757B"
#define W2V_4  "0f3D13757C"
#define W2V_5  "0f3D13757D"
#define W2V_6  "0f3D13757E"
#define W2V_7  "0f3D13757F"
#define W2V_8  "0f3D137580"
#define W2V_9  "0f3D137581"
#define W2V_10 "0f3D137582"
#define W2V_11 "0f3D137583"
#define W2V_12 "0f3D137584"
#define W2V_13 "0f3D137585"
#define W2V_14 "0f3D137586"
#define W2V_15 "0f3D137587"
// W3 = 0.10936080  (0x3DDFF8A9)
#define W3V_0  "0f3DDFF8A9"
#define W3V_1  "0f3DDFF8AA"
#define W3V_2  "0f3DDFF8AB"
#define W3V_3  "0f3DDFF8AC"
#define W3V_4  "0f3DDFF8AD"
#define W3V_5  "0f3DDFF8AE"
#define W3V_6  "0f3DDFF8AF"
#define W3V_7  "0f3DDFF8B0"
#define W3V_8  "0f3DDFF8B1"
#define W3V_9  "0f3DDFF8B2"
#define W3V_10 "0f3DDFF8B3"
#define W3V_11 "0f3DDFF8B4"
#define W3V_12 "0f3DDFF8B5"
#define W3V_13 "0f3DDFF8B6"
#define W3V_14 "0f3DDFF8B7"
#define W3V_15 "0f3DDFF8B8"
// W4 = 0.21300594  (0x3E5A1E3F)
#define W4V_0  "0f3E5A1E3F"
#define W4V_1  "0f3E5A1E40"
#define W4V_2  "0f3E5A1E41"
#define W4V_3  "0f3E5A1E42"
#define W4V_4  "0f3E5A1E43"
#define W4V_5  "0f3E5A1E44"
#define W4V_6  "0f3E5A1E45"
#define W4V_7  "0f3E5A1E46"
#define W4V_8  "0f3E5A1E47"
#define W4V_9  "0f3E5A1E48"
#define W4V_10 "0f3E5A1E49"
#define W4V_11 "0f3E5A1E4A"
#define W4V_12 "0f3E5A1E4B"
#define W4V_13 "0f3E5A1E4C"
#define W4V_14 "0f3E5A1E4D"
#define W4V_15 "0f3E5A1E4E"
// W5 = 0.26601208  (0x3E8832BD)
#define W5V_0  "0f3E8832BD"
#define W5V_1  "0f3E8832BE"
#define W5V_2  "0f3E8832BF"
#define W5V_3  "0f3E8832C0"
#define W5V_4  "0f3E8832C1"
#define W5V_5  "0f3E8832C2"
#define W5V_6  "0f3E8832C3"
#define W5V_7  "0f3E8832C4"

// vertical tap: 4 lanes, per-lane distinct constants
#define VTAP(i, HA, HB, HC, HD) { const float4 v_ = win[r + (i)];      \
    FMA_IMM(a[0], v_.x, HA); FMA_IMM(a[1], v_.y, HB);                  \
    FMA_IMM(a[2], v_.z, HC); FMA_IMM(a[3], v_.w, HD); }

// horizontal tap: 4 outputs, per-output distinct constants
#define HTAP(j, HA, HB, HC, HD) {                                      \
    FMA_IMM(o0, v[(j)],     HA); FMA_IMM(o1, v[(j) + 1], HB);          \
    FMA_IMM(o2, v[(j) + 2], HC); FMA_IMM(o3, v[(j) + 3], HD); }

__device__ __forceinline__ int refl(int i) {
    i = (i < 0) ? -i : i;
    return (i >= IMG) ? (2 * IMG - 2 - i) : i;
}

template<bool SPEC>
__device__ __forceinline__ void blur_body(const float* __restrict__ img,
                                          float* __restrict__ oimg,
                                          int t, int y0, float sig,
                                          float (*s_v)[SVW]) {
    const int x = t << 2;
    const bool edge = (t < 2) || (t >= 126);

    float w[KS];
    if constexpr (!SPEC) {
        float s = fabsf(sig) + 1e-6f;
        float inv = 1.0f / (2.0f * s * s);
        float sum = 0.0f;
        #pragma unroll
        for (int j = 0; j < KS; j++) {
            float r = (float)j - (float)(KS - 1) * 0.5f;
            w[j] = __expf(-r * r * inv);
            sum += w[j];
        }
        float rs = 1.0f / sum;
        #pragma unroll
        for (int j = 0; j < KS; j++) w[j] *= rs;
    }

    float4 win[14];
    #pragma unroll
    for (int k = 0; k < 14; k++)
        win[k] = *(const float4*)(img + (size_t)refl(y0 + k - 5) * IMG + x);

    for (int yb = 0; yb < STRIP; yb += RPT) {
        const int y = y0 + yb;

        float4 pre[RPT];
        #pragma unroll
        for (int r = 0; r < RPT; r++)
            pre[r] = *(const float4*)(img + (size_t)refl(y + 9 + r) * IMG + x);

        // ---- vertical 11-tap (registers only) ----
        #pragma unroll
        for (int r = 0; r < RPT; r++) {
            float a[4] = {0.f, 0.f, 0.f, 0.f};
            if constexpr (SPEC) {
                VTAP(0,  W0V_0,  W0V_1,  W0V_2,  W0V_3)
                VTAP(1,  W1V_0,  W1V_1,  W1V_2,  W1V_3)
                VTAP(2,  W2V_0,  W2V_1,  W2V_2,  W2V_3)
                VTAP(3,  W3V_0,  W3V_1,  W3V_2,  W3V_3)
                VTAP(4,  W4V_0,  W4V_1,  W4V_2,  W4V_3)
                VTAP(5,  W5V_0,  W5V_1,  W5V_2,  W5V_3)
                VTAP(6,  W4V_4,  W4V_5,  W4V_6,  W4V_7)
                VTAP(7,  W3V_4,  W3V_5,  W3V_6,  W3V_7)
                VTAP(8,  W2V_4,  W2V_5,  W2V_6,  W2V_7)
                VTAP(9,  W1V_4,  W1V_5,  W1V_6,  W1V_7)
                VTAP(10, W0V_4,  W0V_5,  W0V_6,  W0V_7)
            } else {
                #pragma unroll
                for (int i = 0; i < KS; i++) {
                    const float  wi = w[i];
                    const float4 v  = win[r + i];
                    a[0] = fmaf(wi, v.x, a[0]);
                    a[1] = fmaf(wi, v.y, a[1]);
                    a[2] = fmaf(wi, v.z, a[2]);
                    a[3] = fmaf(wi, v.w, a[3]);
                }
            }
            float* sv = s_v[r];
            #pragma unroll
            for (int c = 0; c < 4; c++)
                sv[5 + x + c] = a[c];

            if (edge) {
                #pragma unroll
                for (int c = 0; c < 4; c++) {
                    const int xc = x + c;
                    if (xc >= 1   && xc <= 5)   sv[5 - xc]    = a[c];
                    if (xc >= 506 && xc <= 510) sv[1027 - xc] = a[c];
                }
            }
        }
        __syncthreads();

        // ---- horizontal 11-tap: 4 aligned LDS.128 -> 4 outputs per row ----
        #pragma unroll
        for (int r = 0; r < RPT; r++) {
            const float4* vp = (const float4*)&s_v[r][x];
            const float4 A = vp[0], B = vp[1], C = vp[2], D = vp[3];
            const float v[16] = {A.x, A.y, A.z, A.w,
                                 B.x, B.y, B.z, B.w,
                                 C.x, C.y, C.z, C.w,
                                 D.x, D.y, D.z, D.w};
            float o0 = 0.f, o1 = 0.f, o2 = 0.f, o3 = 0.f;
            if constexpr (SPEC) {
                HTAP(0,  W0V_8,  W0V_9,  W0V_10, W0V_11)
                HTAP(1,  W1V_8,  W1V_9,  W1V_10, W1V_11)
                HTAP(2,  W2V_8,  W2V_9,  W2V_10, W2V_11)
                HTAP(3,  W3V_8,  W3V_9,  W3V_10, W3V_11)
                HTAP(4,  W4V_8,  W4V_9,  W4V_10, W4V_11)
                HTAP(5,  W5V_4,  W5V_5,  W5V_6,  W5V_7)
                HTAP(6,  W4V_12, W4V_13, W4V_14, W4V_15)
                HTAP(7,  W3V_12, W3V_13, W3V_14, W3V_15)
                HTAP(8,  W2V_12, W2V_13, W2V_14, W2V_15)
                HTAP(9,  W1V_12, W1V_13, W1V_14, W1V_15)
                HTAP(10, W0V_12, W0V_13, W0V_14, W0V_15)
            } else {
                #pragma unroll
                for (int j = 0; j < KS; j++) {
                    const float wj = w[j];
                    o0 = fmaf(wj, v[j],     o0);
                    o1 = fmaf(wj, v[j + 1], o1);
                    o2 = fmaf(wj, v[j + 2], o2);
                    o3 = fmaf(wj, v[j + 3], o3);
                }
            }
            *(float4*)(oimg + (size_t)(y + r) * IMG + x) = make_float4(o0, o1, o2, o3);
        }
        __syncthreads();

        // ---- slide the window down by RPT rows ----
        #pragma unroll
        for (int k = 0; k < 14 - RPT; k++) win[k] = win[k + RPT];
        #pragma unroll
        for (int r = 0; r < RPT; r++)      win[10 + r] = pre[r];
    }
}

__global__ __launch_bounds__(NT, 5)
void gaussian_blur_kernel(const float* __restrict__ in, float* __restrict__ out,
                          const float* __restrict__ sigma) {
    __shared__ __align__(16) float s_v[RPT][SVW];

    const int t = threadIdx.x;
    const int plane = blockIdx.x >> 2;
    const int y0 = (blockIdx.x & 3) * STRIP;
    const float* __restrict__ img  = in  + (size_t)plane * (IMG * IMG);
    float*       __restrict__ oimg = out + (size_t)plane * (IMG * IMG);

    const float sig = sigma[0];
    if (fabsf(fabsf(sig) - 1.5f) < 1e-4f) {
        blur_body<true >(img, oimg, t, y0, sig, s_v);
    } else {
        blur_body<false>(img, oimg, t, y0, sig, s_v);
    }
}

extern "C" void kernel_launch(void* const* d_in, const int* in_sizes, int n_in,
                              void* d_out, int out_size) {
    const float* x     = (const float*)d_in[0];
    const float* sigma = (const float*)d_in[1];
    float*       out   = (float*)d_out;

    const int n_img = in_sizes[0] / (IMG * IMG);   // B*C planes

    const int strips = IMG / STRIP;                // 4
    gaussian_blur_kernel<<<n_img * strips, NT>>>(x, out, sigma);
}